// round 1
// baseline (speedup 1.0000x reference)
#include <cuda_runtime.h>
#include <math_constants.h>

// Problem shape (fixed by the reference):
//   x:    (16, 64, 512, 512) float32, contiguous  -> per-(b,c) row of HW floats
//   mask: (16, 1, 512, 512) int32                 -> per-b row of HW ints
//   out:  (16, 64) float32
#define NB 16
#define NC 64
#define HW (512 * 512)          // 262144, divisible by everything below
#define CHUNKS 16               // chunks per (b,c) row
#define THREADS 256
#define V4_PER_CHUNK (HW / 4 / CHUNKS)     // 4096 float4 per chunk
#define ITERS (V4_PER_CHUNK / THREADS)     // 16 float4 per thread

// Scratch (no allocation allowed): per-batch unmasked-position counts.
__device__ int g_counts[NB];

// Signed-float atomic max. Requires *addr initialized to -inf.
// pos val: int-compare works (positive floats order like ints; stored -inf is
//          a negative int). neg val: unsigned-compare reverses order for
//          negatives, and any positive stored value has a smaller unsigned
//          pattern than any negative, so atomicMin keeps it.
__device__ __forceinline__ void atomicMaxFloat(float* addr, float val) {
    if (val >= 0.0f) atomicMax((int*)addr, __float_as_int(val));
    else             atomicMin((unsigned int*)addr, __float_as_uint(val));
}

__global__ void init_kernel(float* __restrict__ out) {
    int i = blockIdx.x * blockDim.x + threadIdx.x;
    if (i < NB * NC) out[i] = -CUDART_INF_F;
    if (i < NB) g_counts[i] = 0;
}

__global__ void __launch_bounds__(THREADS)
pool_kernel(const float4* __restrict__ x, const int4* __restrict__ mask,
            float* __restrict__ out) {
    int blk   = blockIdx.x;
    int chunk = blk & (CHUNKS - 1);
    int row   = blk >> 4;           // b*NC + c
    int b     = row >> 6;
    int c     = row & (NC - 1);

    const float4* xr = x + (size_t)row * (HW / 4) + (size_t)chunk * V4_PER_CHUNK;
    const int4*   mr = mask + (size_t)b * (HW / 4) + (size_t)chunk * V4_PER_CHUNK;

    int t = threadIdx.x;
    float vmax = -CUDART_INF_F;
    int cnt = 0;

#pragma unroll
    for (int i = 0; i < ITERS; i++) {
        int idx = i * THREADS + t;       // coalesced across the block
        float4 xv = __ldg(xr + idx);
        int4   mv = __ldg(mr + idx);
        vmax = fmaxf(vmax, mv.x ? xv.x : -CUDART_INF_F);
        vmax = fmaxf(vmax, mv.y ? xv.y : -CUDART_INF_F);
        vmax = fmaxf(vmax, mv.z ? xv.z : -CUDART_INF_F);
        vmax = fmaxf(vmax, mv.w ? xv.w : -CUDART_INF_F);
        cnt += (mv.x != 0) + (mv.y != 0) + (mv.z != 0) + (mv.w != 0);
    }

    // warp reduce max
#pragma unroll
    for (int o = 16; o; o >>= 1)
        vmax = fmaxf(vmax, __shfl_xor_sync(0xffffffffu, vmax, o));
    // count reduce only needed on c==0 blocks (one channel per batch suffices)
    if (c == 0) {
#pragma unroll
        for (int o = 16; o; o >>= 1)
            cnt += __shfl_xor_sync(0xffffffffu, cnt, o);
    }

    __shared__ float smax[THREADS / 32];
    __shared__ int   scnt[THREADS / 32];
    int wid = t >> 5, lid = t & 31;
    if (lid == 0) { smax[wid] = vmax; scnt[wid] = cnt; }
    __syncthreads();

    if (t == 0) {
        float m = smax[0];
#pragma unroll
        for (int w = 1; w < THREADS / 32; w++) m = fmaxf(m, smax[w]);
        atomicMaxFloat(&out[row], m);
        if (c == 0) {
            int s = 0;
#pragma unroll
            for (int w = 0; w < THREADS / 32; w++) s += scnt[w];
            atomicAdd(&g_counts[b], s);
        }
    }
}

__global__ void fixup_kernel(float* __restrict__ out) {
    int i = blockIdx.x * blockDim.x + threadIdx.x;
    if (i < NB * NC) {
        if (g_counts[i >> 6] == 0) out[i] = 0.0f;
    }
}

extern "C" void kernel_launch(void* const* d_in, const int* in_sizes, int n_in,
                              void* d_out, int out_size) {
    const float4* x    = (const float4*)d_in[0];
    const int4*   mask = (const int4*)d_in[1];
    float*        out  = (float*)d_out;

    init_kernel<<<4, 256>>>(out);
    pool_kernel<<<NB * NC * CHUNKS, THREADS>>>(x, mask, out);
    fixup_kernel<<<4, 256>>>(out);
}